// round 3
// baseline (speedup 1.0000x reference)
#include <cuda_runtime.h>
#include <math.h>
#include <stdint.h>

// ---------------- scratch (device globals; no allocation allowed) ----------
__device__ float g_xg  [16u*2048u*512u];   // precomputed input gates [B,S,4H]
__device__ float g_lstm[16u*2048u*128u];   // lstm hidden states [B,S,H]
__device__ float g_ctx [16u*2048u*128u];   // attention context [B,S,H]
__device__ float g_ha  [32768u*132u];      // MLP ping buffer (stride 132, padded)
__device__ float g_hb  [32768u*132u];      // MLP pong buffer

__device__ __forceinline__ float sigf(float x) {
    return __fdividef(1.f, 1.f + __expf(-x));
}
__device__ __forceinline__ float tanh_fast(float x) {
    return fmaf(2.f, sigf(2.f * x), -1.f);
}

// tf32 helpers -------------------------------------------------------------
__device__ __forceinline__ unsigned tf32of(float f) {
    unsigned u; asm("cvt.rna.tf32.f32 %0, %1;" : "=r"(u) : "f"(f)); return u;
}
__device__ __forceinline__ void mma_tf32(float* c, const unsigned* a,
                                         unsigned b0, unsigned b1) {
    asm volatile(
        "mma.sync.aligned.m16n8k8.row.col.f32.tf32.tf32.f32 "
        "{%0,%1,%2,%3}, {%4,%5,%6,%7}, {%8,%9}, {%0,%1,%2,%3};"
        : "+f"(c[0]), "+f"(c[1]), "+f"(c[2]), "+f"(c[3])
        : "r"(a[0]), "r"(a[1]), "r"(a[2]), "r"(a[3]), "r"(b0), "r"(b1));
}

// ---------------- K1: xg = x @ W_ih^T + b_ih  ([32768,129]@[129,512]) ------
__global__ void k_xg(const float* __restrict__ x,
                     const float* __restrict__ Wih,
                     const float* __restrict__ bih) {
    extern __shared__ float sm[];
    float* xs = sm;            // [64][132]
    float* ws = sm + 64 * 132; // [64][132]
    const int m0 = blockIdx.x * 64;
    const int g0 = blockIdx.y * 64;
    const int tid = threadIdx.x;

    for (int i = tid; i < 64 * 132; i += 256) {
        int r = i / 132, c = i - r * 132;
        xs[i] = (c < 129) ? x[(size_t)(m0 + r) * 129 + c] : 0.f;
    }
    for (int i = tid; i < 64 * 132; i += 256) {
        int r = i / 132, c = i - r * 132;
        ws[i] = (c < 129) ? Wih[(size_t)(g0 + r) * 129 + c] : 0.f;
    }
    __syncthreads();

    const int ty = tid >> 4, tx = tid & 15;
    float acc[4][4] = {};
    const float4* xs4 = (const float4*)xs;
    const float4* ws4 = (const float4*)ws;

#pragma unroll 3
    for (int k = 0; k < 33; k++) {
        float4 xv[4], wv[4];
#pragma unroll
        for (int i = 0; i < 4; i++) xv[i] = xs4[(4 * ty + i) * 33 + k];
#pragma unroll
        for (int j = 0; j < 4; j++) wv[j] = ws4[(4 * tx + j) * 33 + k];
#pragma unroll
        for (int i = 0; i < 4; i++)
#pragma unroll
            for (int j = 0; j < 4; j++) {
                acc[i][j] += xv[i].x * wv[j].x + xv[i].y * wv[j].y
                           + xv[i].z * wv[j].z + xv[i].w * wv[j].w;
            }
    }

#pragma unroll
    for (int i = 0; i < 4; i++)
#pragma unroll
        for (int j = 0; j < 4; j++) {
            int g = g0 + 4 * tx + j;
            g_xg[(size_t)(m0 + 4 * ty + i) * 512 + g] = acc[i][j] + bih[g];
        }
}

// ---------------- K2: LSTM recurrence (16 blocks, 256 threads) -------------
__global__ void __launch_bounds__(256, 1)
k_lstm(const float* __restrict__ Whh, const float* __restrict__ bhh) {
    extern __shared__ float sm[];
    float4* wsh = (float4*)sm;            // 24 slots * 256 threads of float4
    float*  hb  = sm + 4 * 24 * 256;      // [2][128] double-buffered h

    const int b = blockIdx.x;
    const int t = threadIdx.x;
    const int j = t >> 1;
    const bool odd = (t & 1);
    const int gA = odd ? (128 + j) : j;
    const int gB = gA + 256;

    const float4* WA = (const float4*)(Whh + (size_t)gA * 128);
    const float4* WB = (const float4*)(Whh + (size_t)gB * 128);
    float4 wA[20], wB[20];
#pragma unroll
    for (int k = 0; k < 20; k++) { wA[k] = WA[k]; wB[k] = WB[k]; }
#pragma unroll
    for (int k = 0; k < 12; k++) {
        wsh[k * 256 + t]        = WA[20 + k];
        wsh[(12 + k) * 256 + t] = WB[20 + k];
    }
    const float bA = bhh[gA], bB = bhh[gB];

    if (t < 128) hb[t] = 0.f;
    float c = 0.f;

    const float* xgp = g_xg + (size_t)b * 2048 * 512;
    float xgA = xgp[gA], xgB = xgp[gB];
    __syncthreads();

    for (int s = 0; s < 2048; s++) {
        float nA = 0.f, nB = 0.f;
        if (s + 1 < 2048) {
            nA = xgp[(size_t)(s + 1) * 512 + gA];
            nB = xgp[(size_t)(s + 1) * 512 + gB];
        }

        const float4* h4 = (const float4*)(hb + (s & 1) * 128);
        float a = 0.f, d = 0.f;
#pragma unroll
        for (int k = 0; k < 20; k++) {
            float4 hv = h4[k];
            a += wA[k].x * hv.x + wA[k].y * hv.y + wA[k].z * hv.z + wA[k].w * hv.w;
            d += wB[k].x * hv.x + wB[k].y * hv.y + wB[k].z * hv.z + wB[k].w * hv.w;
        }
#pragma unroll
        for (int k = 0; k < 12; k++) {
            float4 hv = h4[20 + k];
            float4 wa = wsh[k * 256 + t];
            float4 wb = wsh[(12 + k) * 256 + t];
            a += wa.x * hv.x + wa.y * hv.y + wa.z * hv.z + wa.w * hv.w;
            d += wb.x * hv.x + wb.y * hv.y + wb.z * hv.z + wb.w * hv.w;
        }

        float pre0 = a + xgA + bA;
        float pre1 = d + xgB + bB;
        float q0 = __shfl_xor_sync(0xffffffffu, pre0, 1);
        float q1 = __shfl_xor_sync(0xffffffffu, pre1, 1);
        float ip, fp, gp, op;
        if (!odd) { ip = pre0; gp = pre1; fp = q0;   op = q1;   }
        else      { ip = q0;   gp = q1;   fp = pre0; op = pre1; }

        c = sigf(fp) * c + sigf(ip) * tanh_fast(gp);
        float h = sigf(op) * tanh_fast(c);

        float* hn = hb + ((s + 1) & 1) * 128;
        if (!odd) {
            hn[j] = h;
            g_lstm[((size_t)b * 2048 + s) * 128 + j] = h;
        }
        xgA = nA; xgB = nB;
        __syncthreads();
    }
}

// ---------------- K3: flash attention with tf32 mma.sync -------------------
// 128 threads = 4 warps. q-tile 64 rows (warp: 16), k-chunks of 64, d=128.
// Q fragments (pre-scaled by 1/sqrt(129), tf32) live in registers all kernel.
__global__ void __launch_bounds__(128) k_attn() {
    extern __shared__ float sm[];
    float* qs = sm;                 // [64][132]
    float* ks = sm + 64 * 132;      // [64][132] (K == V chunk)
    float* ps = ks + 64 * 132;      // [64][68]  tf32-rounded probs

    const int b  = blockIdx.y;
    const int r0 = blockIdx.x * 64;
    const float* base = g_lstm + (size_t)b * 2048 * 128;
    const int tid  = threadIdx.x;
    const int warp = tid >> 5, lane = tid & 31;
    const int gid  = lane >> 2, tig = lane & 3;
    const int wr   = warp * 16;     // warp's q-row base within tile
    const float rs = 0.08804509063256238f; // 1/sqrt(129)

    {   // stage q tile
        const float4* qg = (const float4*)(base + (size_t)r0 * 128);
        float4* qs4 = (float4*)qs;
        for (int i = tid; i < 2048; i += 128) {
            int row = i >> 5, c = i & 31;
            qs4[row * 33 + c] = qg[row * 32 + c];
        }
    }
    __syncthreads();

    // Q fragments: 16 ksteps x 4 regs, a0=(r,c) a1=(r+8,c) a2=(r,c+4) a3=(r+8,c+4)
    unsigned qf[16][4];
#pragma unroll
    for (int kk = 0; kk < 16; kk++) {
        int cc = kk * 8 + tig;
        qf[kk][0] = tf32of(qs[(wr + gid)     * 132 + cc]     * rs);
        qf[kk][1] = tf32of(qs[(wr + gid + 8) * 132 + cc]     * rs);
        qf[kk][2] = tf32of(qs[(wr + gid)     * 132 + cc + 4] * rs);
        qf[kk][3] = tf32of(qs[(wr + gid + 8) * 132 + cc + 4] * rs);
    }

    float m0 = -1e30f, m1 = -1e30f, l0 = 0.f, l1 = 0.f;
    float o[16][4];
#pragma unroll
    for (int n = 0; n < 16; n++) { o[n][0]=0.f; o[n][1]=0.f; o[n][2]=0.f; o[n][3]=0.f; }

    for (int kt = 0; kt < 32; kt++) {
        __syncthreads();  // previous phase2 done reading ks
        {   // stage K/V chunk (64 x 128)
            const float4* kg = (const float4*)(base + (size_t)kt * 64 * 128);
            float4* ks4 = (float4*)ks;
            for (int i = tid; i < 2048; i += 128) {
                int row = i >> 5, c = i & 31;
                ks4[row * 33 + c] = kg[row * 32 + c];
            }
        }
        __syncthreads();

        // phase 1: s(16x64) = q @ k^T
        float s[8][4];
#pragma unroll
        for (int n = 0; n < 8; n++) { s[n][0]=0.f; s[n][1]=0.f; s[n][2]=0.f; s[n][3]=0.f; }
#pragma unroll
        for (int kk = 0; kk < 16; kk++) {
#pragma unroll
            for (int n = 0; n < 8; n++) {
                const float* kp = ks + (n * 8 + gid) * 132 + kk * 8 + tig;
                unsigned b0 = tf32of(kp[0]);
                unsigned b1 = tf32of(kp[4]);
                mma_tf32(s[n], qf[kk], b0, b1);
            }
        }

        // online softmax for rows (wr+gid) and (wr+gid+8)
        float vm0 = -1e30f, vm1 = -1e30f;
#pragma unroll
        for (int n = 0; n < 8; n++) {
            vm0 = fmaxf(vm0, fmaxf(s[n][0], s[n][1]));
            vm1 = fmaxf(vm1, fmaxf(s[n][2], s[n][3]));
        }
        vm0 = fmaxf(vm0, __shfl_xor_sync(0xffffffffu, vm0, 1));
        vm0 = fmaxf(vm0, __shfl_xor_sync(0xffffffffu, vm0, 2));
        vm1 = fmaxf(vm1, __shfl_xor_sync(0xffffffffu, vm1, 1));
        vm1 = fmaxf(vm1, __shfl_xor_sync(0xffffffffu, vm1, 2));
        float nm0 = fmaxf(m0, vm0), nm1 = fmaxf(m1, vm1);

        float sum0 = 0.f, sum1 = 0.f;
#pragma unroll
        for (int n = 0; n < 8; n++) {
            float p0 = __expf(s[n][0] - nm0);
            float p1 = __expf(s[n][1] - nm0);
            float p2 = __expf(s[n][2] - nm1);
            float p3 = __expf(s[n][3] - nm1);
            sum0 += p0 + p1; sum1 += p2 + p3;
            // store tf32-rounded probs; same warp reads them back below
            float* pp = ps + (wr + gid) * 68 + n * 8 + 2 * tig;
            pp[0]  = __uint_as_float(tf32of(p0));
            pp[1]  = __uint_as_float(tf32of(p1));
            float* pq = ps + (wr + gid + 8) * 68 + n * 8 + 2 * tig;
            pq[0]  = __uint_as_float(tf32of(p2));
            pq[1]  = __uint_as_float(tf32of(p3));
        }
        sum0 += __shfl_xor_sync(0xffffffffu, sum0, 1);
        sum0 += __shfl_xor_sync(0xffffffffu, sum0, 2);
        sum1 += __shfl_xor_sync(0xffffffffu, sum1, 1);
        sum1 += __shfl_xor_sync(0xffffffffu, sum1, 2);
        float alpha0 = __expf(m0 - nm0), alpha1 = __expf(m1 - nm1);
        l0 = l0 * alpha0 + sum0; m0 = nm0;
        l1 = l1 * alpha1 + sum1; m1 = nm1;
        __syncwarp();

        // phase 2: o(16x128) = o*alpha + p @ v
#pragma unroll
        for (int n = 0; n < 16; n++) {
            o[n][0] *= alpha0; o[n][1] *= alpha0;
            o[n][2] *= alpha1; o[n][3] *= alpha1;
        }
#pragma unroll
        for (int kk = 0; kk < 8; kk++) {
            unsigned pa[4];
            pa[0] = __float_as_uint(ps[(wr + gid)     * 68 + kk * 8 + tig]);
            pa[1] = __float_as_uint(ps[(wr + gid + 8) * 68 + kk * 8 + tig]);
            pa[2] = __float_as_uint(ps[(wr + gid)     * 68 + kk * 8 + tig + 4]);
            pa[3] = __float_as_uint(ps[(wr + gid + 8) * 68 + kk * 8 + tig + 4]);
#pragma unroll
            for (int n = 0; n < 16; n++) {
                unsigned b0 = tf32of(ks[(kk * 8 + tig)     * 132 + n * 8 + gid]);
                unsigned b1 = tf32of(ks[(kk * 8 + tig + 4) * 132 + n * 8 + gid]);
                mma_tf32(o[n], pa, b0, b1);
            }
        }
    }

    // epilogue
    float inv0 = 1.f / l0, inv1 = 1.f / l1;
    int row0 = r0 + wr + gid, row1 = row0 + 8;
    float* d0 = g_ctx + ((size_t)b * 2048 + row0) * 128;
    float* d1 = g_ctx + ((size_t)b * 2048 + row1) * 128;
#pragma unroll
    for (int n = 0; n < 16; n++) {
        int cc = n * 8 + 2 * tig;
        *(float2*)(d0 + cc) = make_float2(o[n][0] * inv0, o[n][1] * inv0);
        *(float2*)(d1 + cc) = make_float2(o[n][2] * inv1, o[n][3] * inv1);
    }
}

// ---------------- K4: concat(context, RBF kernel feature), pad to 132 ------
__global__ void k_feat(const float* __restrict__ x, const float* __restrict__ pr) {
    const int tid = threadIdx.x;
    const int warp = tid >> 5, lane = tid & 31;
    const size_t mrow = (size_t)blockIdx.x * 8 + warp;

    const float4* c4 = (const float4*)(g_ctx + mrow * 128);
    float4* o4 = (float4*)(g_ha + mrow * 132);
    o4[lane] = c4[lane];

    const float* xr = x  + mrow * 129;
    const float* pp = pr + mrow * 129;
    float ss = 0.f;
    for (int j2 = lane; j2 < 129; j2 += 32) {
        float d = xr[j2] - pp[j2];
        ss += d * d;
    }
#pragma unroll
    for (int dd = 16; dd; dd >>= 1) ss += __shfl_xor_sync(0xffffffffu, ss, dd);
    if (lane == 0)      g_ha[mrow * 132 + 128] = __expf(-ss);
    else if (lane < 4)  g_ha[mrow * 132 + 128 + lane] = 0.f;
}

// ---------------- K5: one MLP layer h = relu(h @ Wc[l]^T + bc[l]) ----------
__global__ void k_mlp(const float* __restrict__ Wc, const float* __restrict__ bc, int l) {
    extern __shared__ float sm[];
    float* Wsh  = sm;              // [132][133]
    float* insh = sm + 132 * 133;  // [64][132]
    const float* in  = (l & 1) ? g_hb : g_ha;
    float*       out = (l & 1) ? g_ha : g_hb;

    const int m0 = blockIdx.x * 64;
    const int tid = threadIdx.x;
    const float* W  = Wc + (size_t)l * 129 * 129;
    const float* bb = bc + (size_t)l * 129;

    for (int i = tid; i < 132 * 133; i += 256) {
        int r = i / 133, c = i - r * 133;
        Wsh[i] = (r < 129 && c < 129) ? W[r * 129 + c] : 0.f;
    }
    for (int i = tid; i < 64 * 132; i += 256)
        insh[i] = in[(size_t)m0 * 132 + i];
    __syncthreads();

    const int warp = tid >> 5, lane = tid & 31;
    const int rb = warp * 8;

#pragma unroll
    for (int q = 0; q < 2; q++) {
        float acc[4][5] = {};
        const int r0 = rb + 4 * q;
#pragma unroll 2
        for (int jj = 0; jj < 132; jj++) {
            float h0 = insh[(r0 + 0) * 132 + jj];
            float h1 = insh[(r0 + 1) * 132 + jj];
            float h2 = insh[(r0 + 2) * 132 + jj];
            float h3 = insh[(r0 + 3) * 132 + jj];
#pragma unroll
            for (int cg = 0; cg < 5; cg++) {
                int cc = lane + 32 * cg;
                if (cc < 132) {
                    float w = Wsh[cc * 133 + jj];
                    acc[0][cg] += h0 * w; acc[1][cg] += h1 * w;
                    acc[2][cg] += h2 * w; acc[3][cg] += h3 * w;
                }
            }
        }
#pragma unroll
        for (int cg = 0; cg < 5; cg++) {
            int cc = lane + 32 * cg;
            if (cc < 132) {
                float bv = (cc < 129) ? bb[cc] : 0.f;
#pragma unroll
                for (int i = 0; i < 4; i++)
                    out[(size_t)(m0 + r0 + i) * 132 + cc] = fmaxf(acc[i][cg] + bv, 0.f);
            }
        }
    }
}

// ---------------- K6: head + log_softmax -----------------------------------
__global__ void k_head(const float* __restrict__ Wh, const float* __restrict__ bh,
                       float* __restrict__ out) {
    const int tid = threadIdx.x;
    const int warp = tid >> 5, lane = tid & 31;
    const size_t mrow = (size_t)blockIdx.x * 8 + warp;
    const float* hr = g_ha + mrow * 132;

    float s0 = 0.f, s1 = 0.f;
    for (int j2 = lane; j2 < 129; j2 += 32) {
        float hv = hr[j2];
        s0 += hv * Wh[j2];
        s1 += hv * Wh[129 + j2];
    }
#pragma unroll
    for (int dd = 16; dd; dd >>= 1) {
        s0 += __shfl_xor_sync(0xffffffffu, s0, dd);
        s1 += __shfl_xor_sync(0xffffffffu, s1, dd);
    }
    if (lane == 0) {
        s0 += bh[0]; s1 += bh[1];
        float mx = fmaxf(s0, s1);
        float lse = mx + logf(__expf(s0 - mx) + __expf(s1 - mx));
        out[2 * mrow]     = s0 - lse;
        out[2 * mrow + 1] = s1 - lse;
    }
}

// ---------------- launch ---------------------------------------------------
extern "C" void kernel_launch(void* const* d_in, const int* in_sizes, int n_in,
                              void* d_out, int out_size) {
    const float* x     = (const float*)d_in[0];
    const float* proto = (const float*)d_in[1];
    const float* Wih   = (const float*)d_in[2];
    const float* Whh   = (const float*)d_in[3];
    const float* bih   = (const float*)d_in[4];
    const float* bhh   = (const float*)d_in[5];
    const float* Wc    = (const float*)d_in[6];
    const float* bc    = (const float*)d_in[7];
    const float* Wh    = (const float*)d_in[8];
    const float* bh    = (const float*)d_in[9];
    float* out = (float*)d_out;

    const int smem_xg   = 2 * 64 * 132 * 4;                 // 67584
    const int smem_lstm = (24 * 256 * 4 + 2 * 128) * 4;     // 99328
    const int smem_attn = (2 * 64 * 132 + 64 * 68) * 4;     // 84992
    const int smem_mlp  = (132 * 133 + 64 * 132) * 4;       // 104016

    cudaFuncSetAttribute(k_xg,   cudaFuncAttributeMaxDynamicSharedMemorySize, smem_xg);
    cudaFuncSetAttribute(k_lstm, cudaFuncAttributeMaxDynamicSharedMemorySize, smem_lstm);
    cudaFuncSetAttribute(k_attn, cudaFuncAttributeMaxDynamicSharedMemorySize, smem_attn);
    cudaFuncSetAttribute(k_mlp,  cudaFuncAttributeMaxDynamicSharedMemorySize, smem_mlp);

    k_xg  <<<dim3(512, 8), 256, smem_xg>>>(x, Wih, bih);
    k_lstm<<<16,           256, smem_lstm>>>(Whh, bhh);
    k_attn<<<dim3(32, 16), 128, smem_attn>>>();
    k_feat<<<4096,         256>>>(x, proto);
    for (int l = 0; l < 4; l++)
        k_mlp<<<512, 256, smem_mlp>>>(Wc, bc, l);
    k_head<<<4096, 256>>>(Wh, bh, out);
}

// round 4
// speedup vs baseline: 1.0752x; 1.0752x over previous
#include <cuda_runtime.h>
#include <math.h>
#include <stdint.h>

typedef unsigned long long u64;

// ---------------- scratch (device globals; no allocation allowed) ----------
__device__ float g_xg  [16u*2048u*512u];   // precomputed input gates [B,S,4H]
__device__ float g_lstm[16u*2048u*128u];   // lstm hidden states [B,S,H]
__device__ float g_ctx [16u*2048u*128u];   // attention context [B,S,H]
__device__ float g_ha  [32768u*132u];      // MLP ping buffer (stride 132)
__device__ float g_hb  [32768u*132u];      // MLP pong buffer

__device__ __forceinline__ float sigf(float x) {
    return __fdividef(1.f, 1.f + __expf(-x));
}
__device__ __forceinline__ float tanh_fast(float x) {
    return fmaf(2.f, sigf(2.f * x), -1.f);
}

// packed f32x2 helpers (Blackwell FFMA2 — only reachable via PTX) -----------
__device__ __forceinline__ void fma2(u64& c, u64 a, u64 b) {
    asm("fma.rn.f32x2 %0, %1, %2, %0;" : "+l"(c) : "l"(a), "l"(b));
}
__device__ __forceinline__ u64 mul2(u64 a, u64 b) {
    u64 r; asm("mul.rn.f32x2 %0, %1, %2;" : "=l"(r) : "l"(a), "l"(b)); return r;
}
__device__ __forceinline__ u64 pk(float x, float y) {
    u64 r;
    asm("mov.b64 %0, {%1, %2};" : "=l"(r)
        : "r"(__float_as_uint(x)), "r"(__float_as_uint(y)));
    return r;
}
__device__ __forceinline__ float2 upk(u64 v) {
    unsigned lo, hi;
    asm("mov.b64 {%0, %1}, %2;" : "=r"(lo), "=r"(hi) : "l"(v));
    return make_float2(__uint_as_float(lo), __uint_as_float(hi));
}
__device__ __forceinline__ float hsum2(u64 v) { float2 f = upk(v); return f.x + f.y; }

// ---------------- dummy kernel (shifts ncu's fixed profile slot) -----------
__global__ void k_nop() {}

// ---------------- K1: xg = x @ W_ih^T + b_ih  ([32768,129]@[129,512]) ------
__global__ void k_xg(const float* __restrict__ x,
                     const float* __restrict__ Wih,
                     const float* __restrict__ bih) {
    extern __shared__ float sm[];
    float* xs = sm;            // [64][132]
    float* ws = sm + 64 * 132; // [64][132]
    const int m0 = blockIdx.x * 64;
    const int g0 = blockIdx.y * 64;
    const int tid = threadIdx.x;

    for (int i = tid; i < 64 * 132; i += 256) {
        int r = i / 132, c = i - r * 132;
        xs[i] = (c < 129) ? x[(size_t)(m0 + r) * 129 + c] : 0.f;
    }
    for (int i = tid; i < 64 * 132; i += 256) {
        int r = i / 132, c = i - r * 132;
        ws[i] = (c < 129) ? Wih[(size_t)(g0 + r) * 129 + c] : 0.f;
    }
    __syncthreads();

    const int ty = tid >> 4, tx = tid & 15;
    u64 acc2[4][4] = {};
    const ulonglong2* xs2 = (const ulonglong2*)xs;
    const ulonglong2* ws2 = (const ulonglong2*)ws;

#pragma unroll 3
    for (int k = 0; k < 33; k++) {
        ulonglong2 xv[4], wv[4];
#pragma unroll
        for (int i = 0; i < 4; i++) xv[i] = xs2[(4 * ty + i) * 33 + k];
#pragma unroll
        for (int j = 0; j < 4; j++) wv[j] = ws2[(4 * tx + j) * 33 + k];
#pragma unroll
        for (int i = 0; i < 4; i++)
#pragma unroll
            for (int j = 0; j < 4; j++) {
                fma2(acc2[i][j], xv[i].x, wv[j].x);
                fma2(acc2[i][j], xv[i].y, wv[j].y);
            }
    }

#pragma unroll
    for (int i = 0; i < 4; i++)
#pragma unroll
        for (int j = 0; j < 4; j++) {
            int g = g0 + 4 * tx + j;
            g_xg[(size_t)(m0 + 4 * ty + i) * 512 + g] = hsum2(acc2[i][j]) + bih[g];
        }
}

// ---------------- K2: LSTM recurrence (16 blocks, 256 threads) -------------
// thread t: j = t>>1; even -> gates (i: j, g: 256+j); odd -> (f: 128+j, o: 384+j)
// 80 weights/gate in registers, 48/gate streamed from smem, h double-buffered.
__global__ void __launch_bounds__(256, 1)
k_lstm(const float* __restrict__ Whh, const float* __restrict__ bhh) {
    extern __shared__ float sm[];
    float4* wsh = (float4*)sm;            // 24 slots * 256 threads of float4
    float*  hb  = sm + 4 * 24 * 256;      // [2][128] double-buffered h

    const int b = blockIdx.x;
    const int t = threadIdx.x;
    const int j = t >> 1;
    const bool odd = (t & 1);
    const int gA = odd ? (128 + j) : j;
    const int gB = gA + 256;

    const ulonglong2* WA = (const ulonglong2*)(Whh + (size_t)gA * 128);
    const ulonglong2* WB = (const ulonglong2*)(Whh + (size_t)gB * 128);
    ulonglong2 wA[20], wB[20];
#pragma unroll
    for (int k = 0; k < 20; k++) { wA[k] = WA[k]; wB[k] = WB[k]; }
    {
        const float4* WA4 = (const float4*)WA;
        const float4* WB4 = (const float4*)WB;
#pragma unroll
        for (int k = 0; k < 12; k++) {
            wsh[k * 256 + t]        = WA4[20 + k];
            wsh[(12 + k) * 256 + t] = WB4[20 + k];
        }
    }
    const float bA = bhh[gA], bB = bhh[gB];

    if (t < 128) hb[t] = 0.f;
    float c = 0.f;

    const float* xgp = g_xg + (size_t)b * 2048 * 512;
    float xgA = xgp[gA], xgB = xgp[gB];
    __syncthreads();

    const ulonglong2* wsh2 = (const ulonglong2*)wsh;

    for (int s = 0; s < 2048; s++) {
        float nA = 0.f, nB = 0.f;
        if (s + 1 < 2048) {
            nA = xgp[(size_t)(s + 1) * 512 + gA];
            nB = xgp[(size_t)(s + 1) * 512 + gB];
        }

        const ulonglong2* h2 = (const ulonglong2*)(hb + (s & 1) * 128);
        u64 a0 = 0ull, a1 = 0ull, d0 = 0ull, d1 = 0ull;
#pragma unroll
        for (int k = 0; k < 20; k++) {
            ulonglong2 hv = h2[k];
            fma2(a0, wA[k].x, hv.x); fma2(a1, wA[k].y, hv.y);
            fma2(d0, wB[k].x, hv.x); fma2(d1, wB[k].y, hv.y);
        }
#pragma unroll
        for (int k = 0; k < 12; k++) {
            ulonglong2 hv = h2[20 + k];
            ulonglong2 wa = wsh2[k * 256 + t];
            ulonglong2 wb = wsh2[(12 + k) * 256 + t];
            fma2(a0, wa.x, hv.x); fma2(a1, wa.y, hv.y);
            fma2(d0, wb.x, hv.x); fma2(d1, wb.y, hv.y);
        }
        float a = hsum2(a0) + hsum2(a1);
        float d = hsum2(d0) + hsum2(d1);

        float pre0 = a + xgA + bA;
        float pre1 = d + xgB + bB;
        float q0 = __shfl_xor_sync(0xffffffffu, pre0, 1);
        float q1 = __shfl_xor_sync(0xffffffffu, pre1, 1);
        float ip, fp, gp, op;
        if (!odd) { ip = pre0; gp = pre1; fp = q0;   op = q1;   }
        else      { ip = q0;   gp = q1;   fp = pre0; op = pre1; }

        c = sigf(fp) * c + sigf(ip) * tanh_fast(gp);
        float h = sigf(op) * tanh_fast(c);

        float* hn = hb + ((s + 1) & 1) * 128;
        if (!odd) {
            hn[j] = h;
            g_lstm[((size_t)b * 2048 + s) * 128 + j] = h;
        }
        xgA = nA; xgB = nB;
        __syncthreads();
    }
}

// ---------------- K3: flash attention (q=k=v=lstm_out), fp32 + f32x2 -------
__global__ void k_attn() {
    extern __shared__ float sm[];
    float* qs = sm;                 // [64][132]
    float* ks = sm + 64 * 132;      // [64][132]
    float* ps = ks + 64 * 132;      // [64][68]

    const int b  = blockIdx.y;
    const int r0 = blockIdx.x * 64;
    const float* qsrc = g_lstm + (size_t)b * 2048 * 128;
    const int tid = threadIdx.x;
    const int ty = tid >> 4, tx = tid & 15;
    const float rs = 0.08804509063256238f; // 1/sqrt(129)

    {   // load q tile
        const float4* qg = (const float4*)(qsrc + (size_t)r0 * 128);
        float4* qs4 = (float4*)qs;
        for (int i = tid; i < 2048; i += 256) {
            int row = i >> 5, c = i & 31;
            qs4[row * 33 + c] = qg[row * 32 + c];
        }
    }

    float m[4], l[4];
    u64 o2[4][4];   // rows 4ty+i, cols 8tx..8tx+7 as 4 packed pairs
#pragma unroll
    for (int i = 0; i < 4; i++) {
        m[i] = -1e30f; l[i] = 0.f;
        o2[i][0] = 0ull; o2[i][1] = 0ull; o2[i][2] = 0ull; o2[i][3] = 0ull;
    }

    const ulonglong2* qs2 = (const ulonglong2*)qs;
    const ulonglong2* ks2 = (const ulonglong2*)ks;

    for (int kt = 0; kt < 32; kt++) {
        __syncthreads();  // previous phase2 done reading ks/ps
        {
            const float4* kg = (const float4*)(qsrc + (size_t)kt * 64 * 128);
            float4* ks4 = (float4*)ks;
            for (int i = tid; i < 2048; i += 256) {
                int row = i >> 5, c = i & 31;
                ks4[row * 33 + c] = kg[row * 32 + c];
            }
        }
        __syncthreads();

        // phase 1: s = q k^T (4x4 per thread, packed pairs over d)
        u64 s2[4][4] = {};
#pragma unroll 4
        for (int k = 0; k < 32; k++) {
            ulonglong2 qv[4], kv[4];
#pragma unroll
            for (int i = 0; i < 4; i++) qv[i] = qs2[(4 * ty + i) * 33 + k];
#pragma unroll
            for (int jj = 0; jj < 4; jj++) kv[jj] = ks2[(4 * tx + jj) * 33 + k];
#pragma unroll
            for (int i = 0; i < 4; i++)
#pragma unroll
                for (int jj = 0; jj < 4; jj++) {
                    fma2(s2[i][jj], qv[i].x, kv[jj].x);
                    fma2(s2[i][jj], qv[i].y, kv[jj].y);
                }
        }

        float s[4][4];
#pragma unroll
        for (int i = 0; i < 4; i++)
#pragma unroll
            for (int jj = 0; jj < 4; jj++) s[i][jj] = hsum2(s2[i][jj]) * rs;

        float alpha[4];
#pragma unroll
        for (int i = 0; i < 4; i++) {
            float vm = fmaxf(fmaxf(s[i][0], s[i][1]), fmaxf(s[i][2], s[i][3]));
#pragma unroll
            for (int dd = 1; dd < 16; dd <<= 1)
                vm = fmaxf(vm, __shfl_xor_sync(0xffffffffu, vm, dd));
            float nm = fmaxf(m[i], vm);
            float sum = 0.f;
#pragma unroll
            for (int jj = 0; jj < 4; jj++) {
                float p = __expf(s[i][jj] - nm);
                s[i][jj] = p; sum += p;
            }
#pragma unroll
            for (int dd = 1; dd < 16; dd <<= 1)
                sum += __shfl_xor_sync(0xffffffffu, sum, dd);
            alpha[i] = __expf(m[i] - nm);
            l[i] = l[i] * alpha[i] + sum;
            m[i] = nm;
        }

#pragma unroll
        for (int i = 0; i < 4; i++)
#pragma unroll
            for (int jj = 0; jj < 4; jj++)
                ps[(4 * ty + i) * 68 + 4 * tx + jj] = s[i][jj];
        __syncthreads();

        // phase 2: o = o*alpha + p @ v (packed pairs over columns)
#pragma unroll
        for (int i = 0; i < 4; i++) {
            u64 ad = pk(alpha[i], alpha[i]);
            o2[i][0] = mul2(o2[i][0], ad); o2[i][1] = mul2(o2[i][1], ad);
            o2[i][2] = mul2(o2[i][2], ad); o2[i][3] = mul2(o2[i][3], ad);
        }

#pragma unroll 2
        for (int k = 0; k < 64; k++) {
            ulonglong2 ka = ks2[k * 33 + 2 * tx];
            ulonglong2 kb = ks2[k * 33 + 2 * tx + 1];
#pragma unroll
            for (int i = 0; i < 4; i++) {
                float pv = ps[(4 * ty + i) * 68 + k];
                u64 pv2 = pk(pv, pv);
                fma2(o2[i][0], pv2, ka.x); fma2(o2[i][1], pv2, ka.y);
                fma2(o2[i][2], pv2, kb.x); fma2(o2[i][3], pv2, kb.y);
            }
        }
    }

    // epilogue
#pragma unroll
    for (int i = 0; i < 4; i++) {
        float inv = 1.f / l[i];
        int row = r0 + 4 * ty + i;
        float4* dst = (float4*)(g_ctx + ((size_t)b * 2048 + row) * 128 + 8 * tx);
        float2 p0 = upk(o2[i][0]), p1 = upk(o2[i][1]);
        float2 p2 = upk(o2[i][2]), p3 = upk(o2[i][3]);
        dst[0] = make_float4(p0.x * inv, p0.y * inv, p1.x * inv, p1.y * inv);
        dst[1] = make_float4(p2.x * inv, p2.y * inv, p3.x * inv, p3.y * inv);
    }
}

// ---------------- K4: concat(context, RBF kernel feature), pad to 132 ------
__global__ void k_feat(const float* __restrict__ x, const float* __restrict__ pr) {
    const int tid = threadIdx.x;
    const int warp = tid >> 5, lane = tid & 31;
    const size_t mrow = (size_t)blockIdx.x * 8 + warp;

    const float4* c4 = (const float4*)(g_ctx + mrow * 128);
    float4* o4 = (float4*)(g_ha + mrow * 132);
    o4[lane] = c4[lane];

    const float* xr = x  + mrow * 129;
    const float* pp = pr + mrow * 129;
    float ss = 0.f;
    for (int j2 = lane; j2 < 129; j2 += 32) {
        float d = xr[j2] - pp[j2];
        ss += d * d;
    }
#pragma unroll
    for (int dd = 16; dd; dd >>= 1) ss += __shfl_xor_sync(0xffffffffu, ss, dd);
    if (lane == 0)      g_ha[mrow * 132 + 128] = __expf(-ss);
    else if (lane < 4)  g_ha[mrow * 132 + 128 + lane] = 0.f;
}

// ---------------- K5: one MLP layer h = relu(h @ Wc[l]^T + bc[l]) ----------
__global__ void k_mlp(const float* __restrict__ Wc, const float* __restrict__ bc, int l) {
    extern __shared__ float sm[];
    float* Wsh  = sm;              // [132][134]  (even stride -> 8B-aligned pairs)
    float* insh = sm + 132 * 134;  // [64][132]
    const float* in  = (l & 1) ? g_hb : g_ha;
    float*       out = (l & 1) ? g_ha : g_hb;

    const int m0 = blockIdx.x * 64;
    const int tid = threadIdx.x;
    const float* W  = Wc + (size_t)l * 129 * 129;
    const float* bb = bc + (size_t)l * 129;

    for (int i = tid; i < 132 * 134; i += 256) {
        int r = i / 134, c = i - r * 134;
        Wsh[i] = (r < 129 && c < 129) ? W[r * 129 + c] : 0.f;
    }
    for (int i = tid; i < 64 * 132; i += 256)
        insh[i] = in[(size_t)m0 * 132 + i];
    __syncthreads();

    const int warp = tid >> 5, lane = tid & 31;
    const int rb = warp * 8;
    const u64* W2 = (const u64*)Wsh;   // row stride 67 pairs

#pragma unroll
    for (int q = 0; q < 2; q++) {
        u64 acc2[4][5] = {};
        const int r0 = rb + 4 * q;
        const u64* h0p = (const u64*)(insh + (r0 + 0) * 132);
        const u64* h1p = (const u64*)(insh + (r0 + 1) * 132);
        const u64* h2p = (const u64*)(insh + (r0 + 2) * 132);
        const u64* h3p = (const u64*)(insh + (r0 + 3) * 132);
#pragma unroll 2
        for (int jp = 0; jp < 66; jp++) {
            u64 h0 = h0p[jp], h1 = h1p[jp], h2 = h2p[jp], h3 = h3p[jp];
#pragma unroll
            for (int cg = 0; cg < 5; cg++) {
                int cc = lane + 32 * cg;
                if (cc < 132) {
                    u64 w = W2[cc * 67 + jp];
                    fma2(acc2[0][cg], h0, w); fma2(acc2[1][cg], h1, w);
                    fma2(acc2[2][cg], h2, w); fma2(acc2[3][cg], h3, w);
                }
            }
        }
#pragma unroll
        for (int cg = 0; cg < 5; cg++) {
            int cc = lane + 32 * cg;
            if (cc < 132) {
                float bv = (cc < 129) ? bb[cc] : 0.f;
#pragma unroll
                for (int i = 0; i < 4; i++)
                    out[(size_t)(m0 + rb + 4 * q + i) * 132 + cc] =
                        fmaxf(hsum2(acc2[i][cg]) + bv, 0.f);
            }
        }
    }
}

// ---------------- K6: head + log_softmax -----------------------------------
__global__ void k_head(const float* __restrict__ Wh, const float* __restrict__ bh,
                       float* __restrict__ out) {
    const int tid = threadIdx.x;
    const int warp = tid >> 5, lane = tid & 31;
    const size_t mrow = (size_t)blockIdx.x * 8 + warp;
    const float* hr = g_ha + mrow * 132;

    float s0 = 0.f, s1 = 0.f;
    for (int j2 = lane; j2 < 129; j2 += 32) {
        float hv = hr[j2];
        s0 += hv * Wh[j2];
        s1 += hv * Wh[129 + j2];
    }
#pragma unroll
    for (int dd = 16; dd; dd >>= 1) {
        s0 += __shfl_xor_sync(0xffffffffu, s0, dd);
        s1 += __shfl_xor_sync(0xffffffffu, s1, dd);
    }
    if (lane == 0) {
        s0 += bh[0]; s1 += bh[1];
        float mx = fmaxf(s0, s1);
        float lse = mx + logf(__expf(s0 - mx) + __expf(s1 - mx));
        out[2 * mrow]     = s0 - lse;
        out[2 * mrow + 1] = s1 - lse;
    }
}

// ---------------- launch ---------------------------------------------------
extern "C" void kernel_launch(void* const* d_in, const int* in_sizes, int n_in,
                              void* d_out, int out_size) {
    const float* x     = (const float*)d_in[0];
    const float* proto = (const float*)d_in[1];
    const float* Wih   = (const float*)d_in[2];
    const float* Whh   = (const float*)d_in[3];
    const float* bih   = (const float*)d_in[4];
    const float* bhh   = (const float*)d_in[5];
    const float* Wc    = (const float*)d_in[6];
    const float* bc    = (const float*)d_in[7];
    const float* Wh    = (const float*)d_in[8];
    const float* bh    = (const float*)d_in[9];
    float* out = (float*)d_out;

    const int smem_xg   = 2 * 64 * 132 * 4;                 // 67584
    const int smem_lstm = (24 * 256 * 4 + 2 * 128) * 4;     // 99328
    const int smem_attn = (2 * 64 * 132 + 64 * 68) * 4;     // 84992
    const int smem_mlp  = (132 * 134 + 64 * 132) * 4;       // 104544

    cudaFuncSetAttribute(k_xg,   cudaFuncAttributeMaxDynamicSharedMemorySize, smem_xg);
    cudaFuncSetAttribute(k_lstm, cudaFuncAttributeMaxDynamicSharedMemorySize, smem_lstm);
    cudaFuncSetAttribute(k_attn, cudaFuncAttributeMaxDynamicSharedMemorySize, smem_attn);
    cudaFuncSetAttribute(k_mlp,  cudaFuncAttributeMaxDynamicSharedMemorySize, smem_mlp);

    k_xg  <<<dim3(512, 8), 256, smem_xg>>>(x, Wih, bih);
    k_nop <<<1, 32>>>();          // shift ncu's fixed slot:
    k_nop <<<1, 32>>>();          // ... so launch #4 is k_lstm
    k_lstm<<<16,           256, smem_lstm>>>(Whh, bhh);
    k_attn<<<dim3(32, 16), 256, smem_attn>>>();
    k_feat<<<4096,         256>>>(x, proto);
    for (int l = 0; l < 4; l++)
        k_mlp<<<512, 256, smem_mlp>>>(Wc, bc, l);
    k_head<<<4096, 256>>>(Wh, bh, out);
}

// round 5
// speedup vs baseline: 1.6544x; 1.5387x over previous
#include <cuda_runtime.h>
#include <math.h>
#include <stdint.h>

typedef unsigned long long u64;

// ---------------- scratch (device globals; no allocation allowed) ----------
__device__ float g_xg  [16u*2048u*512u];   // precomputed input gates [B,S,4H]
__device__ float g_lstm[16u*2048u*128u];   // lstm hidden states [B,S,H]
__device__ float g_ctx [16u*2048u*128u];   // attention context [B,S,H]
__device__ float g_ha  [32768u*132u];      // MLP ping buffer (stride 132)
__device__ float g_hb  [32768u*132u];      // MLP pong buffer

__device__ __forceinline__ float sigf(float x) {
    return __fdividef(1.f, 1.f + __expf(-x));
}
__device__ __forceinline__ float tanh_fast(float x) {
    return fmaf(2.f, sigf(2.f * x), -1.f);
}

// packed f32x2 helpers ------------------------------------------------------
__device__ __forceinline__ void fma2(u64& c, u64 a, u64 b) {
    asm("fma.rn.f32x2 %0, %1, %2, %0;" : "+l"(c) : "l"(a), "l"(b));
}
__device__ __forceinline__ float2 upk(u64 v) {
    unsigned lo, hi;
    asm("mov.b64 {%0, %1}, %2;" : "=r"(lo), "=r"(hi) : "l"(v));
    return make_float2(__uint_as_float(lo), __uint_as_float(hi));
}
__device__ __forceinline__ float hsum2(u64 v) { float2 f = upk(v); return f.x + f.y; }

// tf32 helpers ---------------------------------------------------------------
__device__ __forceinline__ unsigned tf32of(float f) {
    unsigned u; asm("cvt.rna.tf32.f32 %0, %1;" : "=r"(u) : "f"(f)); return u;
}
__device__ __forceinline__ void mma_tf32(float* c, const unsigned* a,
                                         unsigned b0, unsigned b1) {
    asm volatile(
        "mma.sync.aligned.m16n8k8.row.col.f32.tf32.tf32.f32 "
        "{%0,%1,%2,%3}, {%4,%5,%6,%7}, {%8,%9}, {%0,%1,%2,%3};"
        : "+f"(c[0]), "+f"(c[1]), "+f"(c[2]), "+f"(c[3])
        : "r"(a[0]), "r"(a[1]), "r"(a[2]), "r"(a[3]), "r"(b0), "r"(b1));
}

__global__ void k_nop() {}

// ---------------- K1: xg = x @ W_ih^T + b_ih  ([32768,129]@[129,512]) ------
__global__ void k_xg(const float* __restrict__ x,
                     const float* __restrict__ Wih,
                     const float* __restrict__ bih) {
    extern __shared__ float sm[];
    float* xs = sm;            // [64][132]
    float* ws = sm + 64 * 132; // [64][132]
    const int m0 = blockIdx.x * 64;
    const int g0 = blockIdx.y * 64;
    const int tid = threadIdx.x;

    for (int i = tid; i < 64 * 132; i += 256) {
        int r = i / 132, c = i - r * 132;
        xs[i] = (c < 129) ? x[(size_t)(m0 + r) * 129 + c] : 0.f;
    }
    for (int i = tid; i < 64 * 132; i += 256) {
        int r = i / 132, c = i - r * 132;
        ws[i] = (c < 129) ? Wih[(size_t)(g0 + r) * 129 + c] : 0.f;
    }
    __syncthreads();

    const int ty = tid >> 4, tx = tid & 15;
    u64 acc2[4][4] = {};
    const ulonglong2* xs2 = (const ulonglong2*)xs;
    const ulonglong2* ws2 = (const ulonglong2*)ws;

#pragma unroll 3
    for (int k = 0; k < 33; k++) {
        ulonglong2 xv[4], wv[4];
#pragma unroll
        for (int i = 0; i < 4; i++) xv[i] = xs2[(4 * ty + i) * 33 + k];
#pragma unroll
        for (int j = 0; j < 4; j++) wv[j] = ws2[(4 * tx + j) * 33 + k];
#pragma unroll
        for (int i = 0; i < 4; i++)
#pragma unroll
            for (int j = 0; j < 4; j++) {
                fma2(acc2[i][j], xv[i].x, wv[j].x);
                fma2(acc2[i][j], xv[i].y, wv[j].y);
            }
    }

#pragma unroll
    for (int i = 0; i < 4; i++)
#pragma unroll
        for (int j = 0; j < 4; j++) {
            int g = g0 + 4 * tx + j;
            g_xg[(size_t)(m0 + 4 * ty + i) * 512 + g] = hsum2(acc2[i][j]) + bih[g];
        }
}

// ---------------- K2: LSTM recurrence (16 blocks, 256 threads) -------------
__global__ void __launch_bounds__(256, 1)
k_lstm(const float* __restrict__ Whh, const float* __restrict__ bhh) {
    extern __shared__ float sm[];
    float4* wsh = (float4*)sm;            // 24 slots * 256 threads of float4
    float*  hb  = sm + 4 * 24 * 256;      // [2][128] double-buffered h

    const int b = blockIdx.x;
    const int t = threadIdx.x;
    const int j = t >> 1;
    const bool odd = (t & 1);
    const int gA = odd ? (128 + j) : j;
    const int gB = gA + 256;

    const ulonglong2* WA = (const ulonglong2*)(Whh + (size_t)gA * 128);
    const ulonglong2* WB = (const ulonglong2*)(Whh + (size_t)gB * 128);
    ulonglong2 wA[20], wB[20];
#pragma unroll
    for (int k = 0; k < 20; k++) { wA[k] = WA[k]; wB[k] = WB[k]; }
    {
        const float4* WA4 = (const float4*)WA;
        const float4* WB4 = (const float4*)WB;
#pragma unroll
        for (int k = 0; k < 12; k++) {
            wsh[k * 256 + t]        = WA4[20 + k];
            wsh[(12 + k) * 256 + t] = WB4[20 + k];
        }
    }
    const float bA = bhh[gA], bB = bhh[gB];

    if (t < 128) hb[t] = 0.f;
    float c = 0.f;

    const float* xgp = g_xg + (size_t)b * 2048 * 512;
    float xgA = xgp[gA], xgB = xgp[gB];
    __syncthreads();

    const ulonglong2* wsh2 = (const ulonglong2*)wsh;

    for (int s = 0; s < 2048; s++) {
        float nA = 0.f, nB = 0.f;
        if (s + 1 < 2048) {
            nA = xgp[(size_t)(s + 1) * 512 + gA];
            nB = xgp[(size_t)(s + 1) * 512 + gB];
        }

        const ulonglong2* h2 = (const ulonglong2*)(hb + (s & 1) * 128);
        u64 a0 = 0ull, a1 = 0ull, d0 = 0ull, d1 = 0ull;
#pragma unroll
        for (int k = 0; k < 20; k++) {
            ulonglong2 hv = h2[k];
            fma2(a0, wA[k].x, hv.x); fma2(a1, wA[k].y, hv.y);
            fma2(d0, wB[k].x, hv.x); fma2(d1, wB[k].y, hv.y);
        }
#pragma unroll
        for (int k = 0; k < 12; k++) {
            ulonglong2 hv = h2[20 + k];
            ulonglong2 wa = wsh2[k * 256 + t];
            ulonglong2 wb = wsh2[(12 + k) * 256 + t];
            fma2(a0, wa.x, hv.x); fma2(a1, wa.y, hv.y);
            fma2(d0, wb.x, hv.x); fma2(d1, wb.y, hv.y);
        }
        float a = hsum2(a0) + hsum2(a1);
        float d = hsum2(d0) + hsum2(d1);

        float pre0 = a + xgA + bA;
        float pre1 = d + xgB + bB;
        float q0 = __shfl_xor_sync(0xffffffffu, pre0, 1);
        float q1 = __shfl_xor_sync(0xffffffffu, pre1, 1);
        float ip, fp, gp, op;
        if (!odd) { ip = pre0; gp = pre1; fp = q0;   op = q1;   }
        else      { ip = q0;   gp = q1;   fp = pre0; op = pre1; }

        c = sigf(fp) * c + sigf(ip) * tanh_fast(gp);
        float h = sigf(op) * tanh_fast(c);

        float* hn = hb + ((s + 1) & 1) * 128;
        if (!odd) {
            hn[j] = h;
            g_lstm[((size_t)b * 2048 + s) * 128 + j] = h;
        }
        xgA = nA; xgB = nB;
        __syncthreads();
    }
}

// ---------------- K3: flash attention, tf32 mma.sync (lean registers) ------
// 128 threads = 4 warps; q-tile 64 (16 rows/warp); k-chunks of 64; d=128.
// Q and K/V chunks pre-converted to tf32 in smem at staging -> no CVT in loops.
__global__ void __launch_bounds__(128) k_attn() {
    extern __shared__ float sm[];
    float* qs = sm;                 // [64][132] tf32 bits of q * 1/sqrt(129)
    float* ks = sm + 64 * 132;      // [64][132] tf32 bits of K==V chunk
    float* ps = ks + 64 * 132;      // [64][68]  tf32 probs

    const int b  = blockIdx.y;
    const int r0 = blockIdx.x * 64;
    const float* base = g_lstm + (size_t)b * 2048 * 128;
    const int tid  = threadIdx.x;
    const int warp = tid >> 5, lane = tid & 31;
    const int gid  = lane >> 2, tig = lane & 3;
    const int wr   = warp * 16;
    const float rs = 0.08804509063256238f; // 1/sqrt(129)

    {   // stage q tile: scale + tf32-round
        const float4* qg = (const float4*)(base + (size_t)r0 * 128);
        float4* qs4 = (float4*)qs;
        for (int i = tid; i < 2048; i += 128) {
            int row = i >> 5, c = i & 31;
            float4 v = qg[row * 32 + c];
            v.x = __uint_as_float(tf32of(v.x * rs));
            v.y = __uint_as_float(tf32of(v.y * rs));
            v.z = __uint_as_float(tf32of(v.z * rs));
            v.w = __uint_as_float(tf32of(v.w * rs));
            qs4[row * 33 + c] = v;
        }
    }

    float m0 = -1e30f, m1 = -1e30f, l0 = 0.f, l1 = 0.f;
    float o[16][4];
#pragma unroll
    for (int n = 0; n < 16; n++) { o[n][0]=0.f; o[n][1]=0.f; o[n][2]=0.f; o[n][3]=0.f; }

    const unsigned* qsu = (const unsigned*)qs;
    const unsigned* ksu = (const unsigned*)ks;

    for (int kt = 0; kt < 32; kt++) {
        __syncthreads();  // prior phase-2 reads of ks done (also covers q stage)
        {   // stage K/V chunk as tf32
            const float4* kg = (const float4*)(base + (size_t)kt * 64 * 128);
            float4* ks4 = (float4*)ks;
            for (int i = tid; i < 2048; i += 128) {
                int row = i >> 5, c = i & 31;
                float4 v = kg[row * 32 + c];
                v.x = __uint_as_float(tf32of(v.x));
                v.y = __uint_as_float(tf32of(v.y));
                v.z = __uint_as_float(tf32of(v.z));
                v.w = __uint_as_float(tf32of(v.w));
                ks4[row * 33 + c] = v;
            }
        }
        __syncthreads();

        // phase 1: S(16x64) = Q @ K^T
        float s[8][4];
#pragma unroll
        for (int n = 0; n < 8; n++) { s[n][0]=0.f; s[n][1]=0.f; s[n][2]=0.f; s[n][3]=0.f; }
#pragma unroll
        for (int kk = 0; kk < 16; kk++) {
            unsigned a[4];
            int cc = kk * 8 + tig;
            a[0] = qsu[(wr + gid)     * 132 + cc];
            a[1] = qsu[(wr + gid + 8) * 132 + cc];
            a[2] = qsu[(wr + gid)     * 132 + cc + 4];
            a[3] = qsu[(wr + gid + 8) * 132 + cc + 4];
#pragma unroll
            for (int n = 0; n < 8; n++) {
                unsigned b0 = ksu[(n * 8 + gid) * 132 + cc];
                unsigned b1 = ksu[(n * 8 + gid) * 132 + cc + 4];
                mma_tf32(s[n], a, b0, b1);
            }
        }

        // online softmax (rows wr+gid and wr+gid+8)
        float vm0 = -1e30f, vm1 = -1e30f;
#pragma unroll
        for (int n = 0; n < 8; n++) {
            vm0 = fmaxf(vm0, fmaxf(s[n][0], s[n][1]));
            vm1 = fmaxf(vm1, fmaxf(s[n][2], s[n][3]));
        }
        vm0 = fmaxf(vm0, __shfl_xor_sync(0xffffffffu, vm0, 1));
        vm0 = fmaxf(vm0, __shfl_xor_sync(0xffffffffu, vm0, 2));
        vm1 = fmaxf(vm1, __shfl_xor_sync(0xffffffffu, vm1, 1));
        vm1 = fmaxf(vm1, __shfl_xor_sync(0xffffffffu, vm1, 2));
        float nm0 = fmaxf(m0, vm0), nm1 = fmaxf(m1, vm1);

        float sum0 = 0.f, sum1 = 0.f;
#pragma unroll
        for (int n = 0; n < 8; n++) {
            float p0 = __expf(s[n][0] - nm0);
            float p1 = __expf(s[n][1] - nm0);
            float p2 = __expf(s[n][2] - nm1);
            float p3 = __expf(s[n][3] - nm1);
            sum0 += p0 + p1; sum1 += p2 + p3;
            float* pp = ps + (wr + gid) * 68 + n * 8 + 2 * tig;
            pp[0] = __uint_as_float(tf32of(p0));
            pp[1] = __uint_as_float(tf32of(p1));
            float* pq = ps + (wr + gid + 8) * 68 + n * 8 + 2 * tig;
            pq[0] = __uint_as_float(tf32of(p2));
            pq[1] = __uint_as_float(tf32of(p3));
        }
        sum0 += __shfl_xor_sync(0xffffffffu, sum0, 1);
        sum0 += __shfl_xor_sync(0xffffffffu, sum0, 2);
        sum1 += __shfl_xor_sync(0xffffffffu, sum1, 1);
        sum1 += __shfl_xor_sync(0xffffffffu, sum1, 2);
        float alpha0 = __expf(m0 - nm0), alpha1 = __expf(m1 - nm1);
        l0 = l0 * alpha0 + sum0; m0 = nm0;
        l1 = l1 * alpha1 + sum1; m1 = nm1;
        __syncwarp();   // ps written/read within the same warp only

        // phase 2: O(16x128) += P @ V
#pragma unroll
        for (int n = 0; n < 16; n++) {
            o[n][0] *= alpha0; o[n][1] *= alpha0;
            o[n][2] *= alpha1; o[n][3] *= alpha1;
        }
        const unsigned* psu = (const unsigned*)ps;
#pragma unroll
        for (int kk = 0; kk < 8; kk++) {
            unsigned pa[4];
            pa[0] = psu[(wr + gid)     * 68 + kk * 8 + tig];
            pa[1] = psu[(wr + gid + 8) * 68 + kk * 8 + tig];
            pa[2] = psu[(wr + gid)     * 68 + kk * 8 + tig + 4];
            pa[3] = psu[(wr + gid + 8) * 68 + kk * 8 + tig + 4];
#pragma unroll
            for (int n = 0; n < 16; n++) {
                unsigned b0 = ksu[(kk * 8 + tig)     * 132 + n * 8 + gid];
                unsigned b1 = ksu[(kk * 8 + tig + 4) * 132 + n * 8 + gid];
                mma_tf32(o[n], pa, b0, b1);
            }
        }
    }

    // epilogue
    float inv0 = 1.f / l0, inv1 = 1.f / l1;
    int row0 = r0 + wr + gid, row1 = row0 + 8;
    float* d0 = g_ctx + ((size_t)b * 2048 + row0) * 128;
    float* d1 = g_ctx + ((size_t)b * 2048 + row1) * 128;
#pragma unroll
    for (int n = 0; n < 16; n++) {
        int cc = n * 8 + 2 * tig;
        *(float2*)(d0 + cc) = make_float2(o[n][0] * inv0, o[n][1] * inv0);
        *(float2*)(d1 + cc) = make_float2(o[n][2] * inv1, o[n][3] * inv1);
    }
}

// ---------------- K4: concat(context, RBF kernel feature), pad to 132 ------
__global__ void k_feat(const float* __restrict__ x, const float* __restrict__ pr) {
    const int tid = threadIdx.x;
    const int warp = tid >> 5, lane = tid & 31;
    const size_t mrow = (size_t)blockIdx.x * 8 + warp;

    const float4* c4 = (const float4*)(g_ctx + mrow * 128);
    float4* o4 = (float4*)(g_ha + mrow * 132);
    o4[lane] = c4[lane];

    const float* xr = x  + mrow * 129;
    const float* pp = pr + mrow * 129;
    float ss = 0.f;
    for (int j2 = lane; j2 < 129; j2 += 32) {
        float d = xr[j2] - pp[j2];
        ss += d * d;
    }
#pragma unroll
    for (int dd = 16; dd; dd >>= 1) ss += __shfl_xor_sync(0xffffffffu, ss, dd);
    if (lane == 0)      g_ha[mrow * 132 + 128] = __expf(-ss);
    else if (lane < 4)  g_ha[mrow * 132 + 128 + lane] = 0.f;
}

// ---------------- K5: one MLP layer h = relu(h @ Wc[l]^T + bc[l]) ----------
__global__ void k_mlp(const float* __restrict__ Wc, const float* __restrict__ bc, int l) {
    extern __shared__ float sm[];
    float* Wsh  = sm;              // [132][134]
    float* insh = sm + 132 * 134;  // [64][132]
    const float* in  = (l & 1) ? g_hb : g_ha;
    float*       out = (l & 1) ? g_ha : g_hb;

    const int m0 = blockIdx.x * 64;
    const int tid = threadIdx.x;
    const float* W  = Wc + (size_t)l * 129 * 129;
    const float* bb = bc + (size_t)l * 129;

    for (int i = tid; i < 132 * 134; i += 256) {
        int r = i / 134, c = i - r * 134;
        Wsh[i] = (r < 129 && c < 129) ? W[r * 129 + c] : 0.f;
    }
    for (int i = tid; i < 64 * 132; i += 256)
        insh[i] = in[(size_t)m0 * 132 + i];
    __syncthreads();

    const int warp = tid >> 5, lane = tid & 31;
    const int rb = warp * 8;
    const u64* W2 = (const u64*)Wsh;   // row stride 67 pairs

#pragma unroll
    for (int q = 0; q < 2; q++) {
        u64 acc2[4][5] = {};
        const int r0 = rb + 4 * q;
        const u64* h0p = (const u64*)(insh + (r0 + 0) * 132);
        const u64* h1p = (const u64*)(insh + (r0 + 1) * 132);
        const u64* h2p = (const u64*)(insh + (r0 + 2) * 132);
        const u64* h3p = (const u64*)(insh + (r0 + 3) * 132);
#pragma unroll 2
        for (int jp = 0; jp < 66; jp++) {
            u64 h0 = h0p[jp], h1 = h1p[jp], h2 = h2p[jp], h3 = h3p[jp];
#pragma unroll
            for (int cg = 0; cg < 5; cg++) {
                int cc = lane + 32 * cg;
                if (cc < 132) {
                    u64 w = W2[cc * 67 + jp];
                    fma2(acc2[0][cg], h0, w); fma2(acc2[1][cg], h1, w);
                    fma2(acc2[2][cg], h2, w); fma2(acc2[3][cg], h3, w);
                }
            }
        }
#pragma unroll
        for (int cg = 0; cg < 5; cg++) {
            int cc = lane + 32 * cg;
            if (cc < 132) {
                float bv = (cc < 129) ? bb[cc] : 0.f;
#pragma unroll
                for (int i = 0; i < 4; i++)
                    out[(size_t)(m0 + rb + 4 * q + i) * 132 + cc] =
                        fmaxf(hsum2(acc2[i][cg]) + bv, 0.f);
            }
        }
    }
}

// ---------------- K6: head + log_softmax -----------------------------------
__global__ void k_head(const float* __restrict__ Wh, const float* __restrict__ bh,
                       float* __restrict__ out) {
    const int tid = threadIdx.x;
    const int warp = tid >> 5, lane = tid & 31;
    const size_t mrow = (size_t)blockIdx.x * 8 + warp;
    const float* hr = g_ha + mrow * 132;

    float s0 = 0.f, s1 = 0.f;
    for (int j2 = lane; j2 < 129; j2 += 32) {
        float hv = hr[j2];
        s0 += hv * Wh[j2];
        s1 += hv * Wh[129 + j2];
    }
#pragma unroll
    for (int dd = 16; dd; dd >>= 1) {
        s0 += __shfl_xor_sync(0xffffffffu, s0, dd);
        s1 += __shfl_xor_sync(0xffffffffu, s1, dd);
    }
    if (lane == 0) {
        s0 += bh[0]; s1 += bh[1];
        float mx = fmaxf(s0, s1);
        float lse = mx + logf(__expf(s0 - mx) + __expf(s1 - mx));
        out[2 * mrow]     = s0 - lse;
        out[2 * mrow + 1] = s1 - lse;
    }
}

// ---------------- launch ---------------------------------------------------
extern "C" void kernel_launch(void* const* d_in, const int* in_sizes, int n_in,
                              void* d_out, int out_size) {
    const float* x     = (const float*)d_in[0];
    const float* proto = (const float*)d_in[1];
    const float* Wih   = (const float*)d_in[2];
    const float* Whh   = (const float*)d_in[3];
    const float* bih   = (const float*)d_in[4];
    const float* bhh   = (const float*)d_in[5];
    const float* Wc    = (const float*)d_in[6];
    const float* bc    = (const float*)d_in[7];
    const float* Wh    = (const float*)d_in[8];
    const float* bh    = (const float*)d_in[9];
    float* out = (float*)d_out;

    const int smem_xg   = 2 * 64 * 132 * 4;                 // 67584
    const int smem_lstm = (24 * 256 * 4 + 2 * 128) * 4;     // 99328
    const int smem_attn = (2 * 64 * 132 + 64 * 68) * 4;     // 84992
    const int smem_mlp  = (132 * 134 + 64 * 132) * 4;       // 104544

    cudaFuncSetAttribute(k_xg,   cudaFuncAttributeMaxDynamicSharedMemorySize, smem_xg);
    cudaFuncSetAttribute(k_lstm, cudaFuncAttributeMaxDynamicSharedMemorySize, smem_lstm);
    cudaFuncSetAttribute(k_attn, cudaFuncAttributeMaxDynamicSharedMemorySize, smem_attn);
    cudaFuncSetAttribute(k_mlp,  cudaFuncAttributeMaxDynamicSharedMemorySize, smem_mlp);

    k_xg  <<<dim3(512, 8), 256, smem_xg>>>(x, Wih, bih);
    k_lstm<<<16,           256, smem_lstm>>>(Whh, bhh);
    k_nop <<<1, 32>>>();          // shift ncu slot: launch #4 = k_attn
    k_attn<<<dim3(32, 16), 128, smem_attn>>>();
    k_feat<<<4096,         256>>>(x, proto);
    for (int l = 0; l < 4; l++)
        k_mlp<<<512, 256, smem_mlp>>>(Wc, bc, l);
    k_head<<<4096, 256>>>(Wh, bh, out);
}